// round 1
// baseline (speedup 1.0000x reference)
#include <cuda_runtime.h>
#include <cuda_bf16.h>
#include <stdint.h>

// ---------------------------------------------------------------------------
// HeteroGraphSAGE, 2 layers, 4 node types, 8 relations.
// Node layout (concatenated): user[200000] | product[100000] | category[2000] | query[50000]
// ---------------------------------------------------------------------------

#define NU 200000
#define NP 100000
#define NC 2000
#define NQ 50000
#define NTOT 352000
#define HID 128

// scratch (device globals; allocation-free)
__device__ float g_y[(size_t)NU * HID];          // transformed-src buffer (max src = user)
__device__ float g_acc[(size_t)NTOT * HID];      // per-dst accumulator (all types)
__device__ float g_h[(size_t)NTOT * HID];        // hidden after layer 1
__device__ float g_inv[802000];                  // per-relation 1/max(cnt,1)
__device__ float g_wsum[2 * 4 * HID * HID];      // combined Wl per (layer, dst type)
__device__ float g_bsum[2 * 4 * HID];            // combined bias per (layer, dst type)

// ---------------------------------------------------------------------------
// GEMM: C[i][:] = optional(addsrc[i][:]) + bias[:] + A[i][:] @ W^T   (K=N=128)
// fp32 SIMT, 128-row tiles, 8x8 per-thread microtile.
// ---------------------------------------------------------------------------
__global__ void __launch_bounds__(256, 2)
gemm_n128(const float* __restrict__ A, const float* __restrict__ W,
          const float* __restrict__ addsrc, const float* __restrict__ bias,
          float* __restrict__ C, int n, int dorelu)
{
    __shared__ __align__(16) float As[128][33];   // [row][k] natural layout
    __shared__ __align__(16) float Ws[32][132];   // [k][col] transposed

    const int tid = threadIdx.x;
    const int tx = tid & 15;      // col group
    const int ty = tid >> 4;      // row group
    const int bm = blockIdx.x * 128;

    float cacc[8][8];
#pragma unroll
    for (int i = 0; i < 8; i++)
#pragma unroll
        for (int j = 0; j < 8; j++) cacc[i][j] = 0.f;

    for (int kb = 0; kb < 128; kb += 32) {
        // load A chunk (128 rows x 32 k), coalesced, natural layout
#pragma unroll
        for (int i = 0; i < 16; i++) {
            int idx = tid + i * 256;       // 0..4095
            int r = idx >> 5;
            int c = idx & 31;
            int row = bm + r;
            As[r][c] = (row < n) ? A[(size_t)row * HID + kb + c] : 0.f;
        }
        // load W chunk transposed: Ws[k][j] = W[j][kb+k]
#pragma unroll
        for (int i = 0; i < 16; i++) {
            int idx = tid + i * 256;
            int j = idx >> 5;
            int c = idx & 31;
            Ws[c][j] = W[j * HID + kb + c];
        }
        __syncthreads();

#pragma unroll
        for (int k = 0; k < 32; k++) {
            float a[8], b[8];
#pragma unroll
            for (int i = 0; i < 8; i++) a[i] = As[ty * 8 + i][k];
            float4 b0 = *(const float4*)&Ws[k][tx * 8];
            float4 b1 = *(const float4*)&Ws[k][tx * 8 + 4];
            b[0] = b0.x; b[1] = b0.y; b[2] = b0.z; b[3] = b0.w;
            b[4] = b1.x; b[5] = b1.y; b[6] = b1.z; b[7] = b1.w;
#pragma unroll
            for (int i = 0; i < 8; i++)
#pragma unroll
                for (int j = 0; j < 8; j++)
                    cacc[i][j] += a[i] * b[j];
        }
        __syncthreads();
    }

    // epilogue
#pragma unroll
    for (int i = 0; i < 8; i++) {
        int row = bm + ty * 8 + i;
        if (row < n) {
#pragma unroll
            for (int j = 0; j < 8; j++) {
                int col = tx * 8 + j;
                float v = cacc[i][j];
                if (bias)   v += bias[col];
                if (addsrc) v += addsrc[(size_t)row * HID + col];
                if (dorelu) v = fmaxf(v, 0.f);
                C[(size_t)row * HID + col] = v;
            }
        }
    }
}

// ---------------------------------------------------------------------------
// Edge degree count (float, matches segment_sum of ones)
// ---------------------------------------------------------------------------
__global__ void count_kernel(const int* __restrict__ dst, int E, float* __restrict__ cnt)
{
    int e = blockIdx.x * blockDim.x + threadIdx.x;
    if (e < E) atomicAdd(&cnt[dst[e]], 1.0f);
}

__global__ void inv_kernel(float* __restrict__ c, int n)
{
    int i = blockIdx.x * blockDim.x + threadIdx.x;
    if (i < n) c[i] = 1.0f / fmaxf(c[i], 1.0f);
}

// ---------------------------------------------------------------------------
// Combined Wl / bias per (layer, dst type). dst type of relation t:
//   t: 0..7 -> {product,user,query,user,product,query,category,product}
// ---------------------------------------------------------------------------
__global__ void wsum_kernel(const float* __restrict__ W1l, const float* __restrict__ b1,
                            const float* __restrict__ W2l, const float* __restrict__ b2,
                            float* __restrict__ wsum, float* __restrict__ bsum)
{
    const int dstT[8] = {1, 0, 3, 0, 1, 3, 2, 1};
    int idx = blockIdx.x * blockDim.x + threadIdx.x;     // 0 .. 2*4*16384-1
    if (idx >= 2 * 4 * HID * HID) return;
    int l  = idx / (4 * HID * HID);
    int r  = idx % (4 * HID * HID);
    int d  = r / (HID * HID);
    int ij = r % (HID * HID);
    const float* W = l ? W2l : W1l;
    float s = 0.f;
#pragma unroll
    for (int t = 0; t < 8; t++)
        if (dstT[t] == d) s += W[t * HID * HID + ij];
    wsum[idx] = s;
    if (ij < HID) {
        const float* B = l ? b2 : b1;
        float sb = 0.f;
#pragma unroll
        for (int t = 0; t < 8; t++)
            if (dstT[t] == d) sb += B[t * HID + ij];
        bsum[(l * 4 + d) * HID + ij] = sb;
    }
}

// ---------------------------------------------------------------------------
// Edge scatter: one warp per edge.
//   acc[dst][:] += y[src][:] * (w[e] * inv[dst])
// ---------------------------------------------------------------------------
__global__ void scatter_kernel(const float* __restrict__ y,
                               const int* __restrict__ src_idx,
                               const int* __restrict__ dst_idx,
                               const float* __restrict__ ew,
                               const float* __restrict__ inv,
                               float* __restrict__ acc, int E)
{
    int gw = (blockIdx.x * blockDim.x + threadIdx.x) >> 5;
    int lane = threadIdx.x & 31;
    if (gw >= E) return;
    int s = src_idx[gw];
    int d = dst_idx[gw];
    float sc = ew[gw] * inv[d];
    const float* yr = y + (size_t)s * HID;
    float* ar = acc + (size_t)d * HID;
#pragma unroll
    for (int q = 0; q < 4; q++) {
        float v = yr[lane + 32 * q];
        atomicAdd(&ar[lane + 32 * q], v * sc);
    }
}

// ---------------------------------------------------------------------------
// Host launch
// ---------------------------------------------------------------------------
struct Rel { int srcT, dstT, E, eiIdx, rev, ewIdx, invOff; };

extern "C" void kernel_launch(void* const* d_in, const int* in_sizes, int n_in,
                              void* d_out, int out_size)
{
    (void)in_sizes; (void)n_in; (void)out_size;

    static const Rel rels[8] = {
        {0, 1, 500000, 18, 0, 10, 0},       // user -> product  (buys)
        {1, 0, 500000, 18, 1, 11, 100000},  // product -> user  (rev buys)
        {0, 3, 300000, 19, 0, 12, 300000},  // user -> query    (searches)
        {3, 0, 300000, 19, 1, 13, 350000},  // query -> user    (rev searches)
        {3, 1, 300000, 20, 0, 14, 550000},  // query -> product (matches)
        {1, 3, 300000, 20, 1, 15, 650000},  // product -> query (rev matches)
        {1, 2, 100000, 21, 0, 16, 700000},  // product -> category (in)
        {2, 1, 100000, 21, 1, 17, 702000},  // category -> product (rev in)
    };
    static const int    nodeN[4]   = {NU, NP, NC, NQ};
    static const size_t nodeOff[4] = {0, NU, NU + NP, NU + NP + NC};

    float *y, *acc, *h, *inv, *wsum, *bsum;
    cudaGetSymbolAddress((void**)&y,    g_y);
    cudaGetSymbolAddress((void**)&acc,  g_acc);
    cudaGetSymbolAddress((void**)&h,    g_h);
    cudaGetSymbolAddress((void**)&inv,  g_inv);
    cudaGetSymbolAddress((void**)&wsum, g_wsum);
    cudaGetSymbolAddress((void**)&bsum, g_bsum);

    const float* x0[4] = { (const float*)d_in[0], (const float*)d_in[1],
                           (const float*)d_in[2], (const float*)d_in[3] };
    const float* W1l = (const float*)d_in[4];
    const float* b1  = (const float*)d_in[5];
    const float* W1r = (const float*)d_in[6];
    const float* W2l = (const float*)d_in[7];
    const float* b2  = (const float*)d_in[8];
    const float* W2r = (const float*)d_in[9];
    float* out = (float*)d_out;

    cudaStream_t st = 0;

    // ---- counts -> inverse (edge structure is layer-invariant) ----
    cudaMemsetAsync(inv, 0, 802000 * sizeof(float), st);
    for (int t = 0; t < 8; t++) {
        const Rel& r = rels[t];
        const int* ei  = (const int*)d_in[r.eiIdx];
        const int* dst = r.rev ? ei : ei + r.E;
        count_kernel<<<(r.E + 255) / 256, 256, 0, st>>>(dst, r.E, inv + r.invOff);
    }
    inv_kernel<<<(802000 + 255) / 256, 256, 0, st>>>(inv, 802000);

    // ---- combined Wl / bias ----
    wsum_kernel<<<(2 * 4 * HID * HID + 255) / 256, 256, 0, st>>>(W1l, b1, W2l, b2, wsum, bsum);

    // ---- two layers ----
    for (int layer = 0; layer < 2; layer++) {
        const float* Wr   = layer ? W2r : W1r;
        const float** xin = layer ? (const float**)nullptr : x0; // resolved below
        cudaMemsetAsync(acc, 0, (size_t)NTOT * HID * sizeof(float), st);

        for (int t = 0; t < 8; t++) {
            const Rel& r = rels[t];
            const float* A = layer ? (h + nodeOff[r.srcT] * HID) : x0[r.srcT];
            int nsrc = nodeN[r.srcT];
            gemm_n128<<<(nsrc + 127) / 128, 256, 0, st>>>(
                A, Wr + t * HID * HID, nullptr, nullptr, y, nsrc, 0);

            const int* ei  = (const int*)d_in[r.eiIdx];
            const int* src = r.rev ? ei + r.E : ei;
            const int* dst = r.rev ? ei       : ei + r.E;
            const float* ew = (const float*)d_in[r.ewIdx];
            int nwarps = r.E;
            scatter_kernel<<<(nwarps * 32 + 255) / 256, 256, 0, st>>>(
                y, src, dst, ew, inv + r.invOff, acc + nodeOff[r.dstT] * HID, r.E);
        }

        for (int d = 0; d < 4; d++) {
            const float* A = layer ? (h + nodeOff[d] * HID) : x0[d];
            float* C = layer ? (out + nodeOff[d] * HID) : (h + nodeOff[d] * HID);
            gemm_n128<<<(nodeN[d] + 127) / 128, 256, 0, st>>>(
                A, wsum + (layer * 4 + d) * HID * HID, acc + nodeOff[d] * HID,
                bsum + (layer * 4 + d) * HID, C, nodeN[d], layer == 0 ? 1 : 0);
        }
        (void)xin;
    }
}

// round 2
// speedup vs baseline: 2.0316x; 2.0316x over previous
#include <cuda_runtime.h>
#include <cuda_bf16.h>
#include <stdint.h>

// ---------------------------------------------------------------------------
// HeteroGraphSAGE, 2 layers, 4 node types, 8 relations.
// Node layout (concatenated): user[200000] | product[100000] | category[2000] | query[50000]
// ---------------------------------------------------------------------------

#define NU 200000
#define NP 100000
#define NC 2000
#define NQ 50000
#define NTOT 352000
#define HID 128

#define LDS 72            // bf16 elems per smem row (64 data + 8 pad -> 144B stride)
#define LDSB 144
#define SMEM_BYTES (4 * 128 * LDS * 2)   // Ah, Al, Wh, Wl

// scratch (device globals; allocation-free)
__device__ float g_y[(size_t)NU * HID];          // transformed-src buffer (max src = user)
__device__ float g_acc[(size_t)NTOT * HID];      // per-dst accumulator (all types)
__device__ float g_h[(size_t)NTOT * HID];        // hidden after layer 1
__device__ float g_inv[802000];                  // per-relation 1/max(cnt,1)
__device__ float g_wsum[2 * 4 * HID * HID];      // combined Wl per (layer, dst type)
__device__ float g_bsum[2 * 4 * HID];            // combined bias per (layer, dst type)

// ---------------------------------------------------------------------------
// PTX helpers
// ---------------------------------------------------------------------------
#define LDSM4(R, addr)                                                          \
    asm volatile("ldmatrix.sync.aligned.m8n8.x4.shared.b16 {%0,%1,%2,%3}, [%4];" \
                 : "=r"((R)[0]), "=r"((R)[1]), "=r"((R)[2]), "=r"((R)[3])        \
                 : "r"(addr))

#define MMA16816(C, A, B0, B1)                                                  \
    asm volatile("mma.sync.aligned.m16n8k16.row.col.f32.bf16.bf16.f32 "         \
                 "{%0,%1,%2,%3},{%4,%5,%6,%7},{%8,%9},{%0,%1,%2,%3};"           \
                 : "+f"((C)[0]), "+f"((C)[1]), "+f"((C)[2]), "+f"((C)[3])        \
                 : "r"((A)[0]), "r"((A)[1]), "r"((A)[2]), "r"((A)[3]),           \
                   "r"(B0), "r"(B1))

__device__ __forceinline__ uint32_t pack_bf16(__nv_bfloat16 a, __nv_bfloat16 b)
{
    __nv_bfloat162 p = __halves2bfloat162(a, b);
    return *reinterpret_cast<uint32_t*>(&p);
}

__device__ __forceinline__ void split_pair(float x, float y, uint32_t& hi, uint32_t& lo)
{
    __nv_bfloat16 hx = __float2bfloat16(x);
    __nv_bfloat16 hy = __float2bfloat16(y);
    __nv_bfloat16 lx = __float2bfloat16(x - __bfloat162float(hx));
    __nv_bfloat16 ly = __float2bfloat16(y - __bfloat162float(hy));
    hi = pack_bf16(hx, hy);
    lo = pack_bf16(lx, ly);
}

// ---------------------------------------------------------------------------
// Tensor-core GEMM (bf16x3 split, fp32-accurate to ~2^-16):
//   C[i][:] = optional(addsrc[i][:]) + optional(bias[:]) + A[i][:] @ W^T
// Block tile 128x128, warp tile 32x64 (8 warps, 4m x 2n), K chunked by 64.
// ---------------------------------------------------------------------------
__global__ void __launch_bounds__(256, 2)
gemm_mma(const float* __restrict__ A, const float* __restrict__ W,
         const float* __restrict__ addsrc, const float* __restrict__ bias,
         float* __restrict__ C, int n, int dorelu)
{
    extern __shared__ __nv_bfloat16 smem[];
    // layout: Ah[128*LDS] | Al | Wh | Wl
    uint32_t sAh_u = (uint32_t)__cvta_generic_to_shared(smem);
    const uint32_t LO_OFF = 128 * LDS * 2;       // bytes from hi array to lo array
    uint32_t sWh_u = sAh_u + 2 * LO_OFF;

    const int tid  = threadIdx.x;
    const int lane = tid & 31;
    const int warp = tid >> 5;
    const int wm = warp >> 1;       // 0..3  (rows)
    const int wn = warp & 1;        // 0..1  (cols)
    const int bm = blockIdx.x * 128;

    float c[2][8][4];
#pragma unroll
    for (int i = 0; i < 2; i++)
#pragma unroll
        for (int j = 0; j < 8; j++)
#pragma unroll
            for (int q = 0; q < 4; q++) c[i][j][q] = 0.f;

    for (int kb = 0; kb < 128; kb += 64) {
        // ---- load + convert A chunk (128 x 64) and W chunk (128 x 64) ----
#pragma unroll
        for (int it = 0; it < 8; it++) {
            int idx = tid + it * 256;          // float4 id 0..2047
            int r   = idx >> 4;                // row 0..127
            int kc  = (idx & 15) << 2;         // k within chunk, mult of 4

            float4 va = make_float4(0.f, 0.f, 0.f, 0.f);
            int row = bm + r;
            if (row < n)
                va = *(const float4*)(A + (size_t)row * HID + kb + kc);
            uint32_t h01, l01, h23, l23;
            split_pair(va.x, va.y, h01, l01);
            split_pair(va.z, va.w, h23, l23);
            size_t so = (size_t)r * LDS + kc;
            *(uint2*)(smem + so)                 = make_uint2(h01, h23);
            *(uint2*)(smem + 128 * LDS + so)     = make_uint2(l01, l23);

            float4 vw = *(const float4*)(W + (size_t)r * HID + kb + kc);
            split_pair(vw.x, vw.y, h01, l01);
            split_pair(vw.z, vw.w, h23, l23);
            *(uint2*)(smem + 2 * 128 * LDS + so) = make_uint2(h01, h23);
            *(uint2*)(smem + 3 * 128 * LDS + so) = make_uint2(l01, l23);
        }
        __syncthreads();

        // ---- 4 k-steps of 16 within this 64-chunk ----
#pragma unroll
        for (int ks = 0; ks < 4; ks++) {
            uint32_t ah[2][4], al[2][4], bh[4][4], bl[4][4];

#pragma unroll
            for (int i = 0; i < 2; i++) {
                int r   = wm * 32 + i * 16 + (lane & 15);
                int kby = ks * 32 + ((lane >> 4) << 4);
                uint32_t ad = sAh_u + r * LDSB + kby;
                LDSM4(ah[i], ad);
                LDSM4(al[i], ad + LO_OFF);
            }
#pragma unroll
            for (int p = 0; p < 4; p++) {
                int nr  = wn * 64 + (2 * p + (lane >> 4)) * 8 + (lane & 7);
                int kby = ks * 32 + ((lane >> 3) & 1) * 16;
                uint32_t ad = sWh_u + nr * LDSB + kby;
                LDSM4(bh[p], ad);
                LDSM4(bl[p], ad + LO_OFF);
            }

#pragma unroll
            for (int i = 0; i < 2; i++)
#pragma unroll
                for (int j = 0; j < 8; j++) {
                    const uint32_t* b = bh[j >> 1] + (j & 1) * 2;
                    MMA16816(c[i][j], ah[i], b[0], b[1]);
                }
#pragma unroll
            for (int i = 0; i < 2; i++)
#pragma unroll
                for (int j = 0; j < 8; j++) {
                    const uint32_t* b = bl[j >> 1] + (j & 1) * 2;
                    MMA16816(c[i][j], ah[i], b[0], b[1]);
                }
#pragma unroll
            for (int i = 0; i < 2; i++)
#pragma unroll
                for (int j = 0; j < 8; j++) {
                    const uint32_t* b = bh[j >> 1] + (j & 1) * 2;
                    MMA16816(c[i][j], al[i], b[0], b[1]);
                }
        }
        __syncthreads();
    }

    // ---- epilogue ----
    const int g  = lane >> 2;
    const int tq = lane & 3;
#pragma unroll
    for (int i = 0; i < 2; i++) {
#pragma unroll
        for (int half = 0; half < 2; half++) {
            int row = bm + wm * 32 + i * 16 + half * 8 + g;
            if (row >= n) continue;
#pragma unroll
            for (int j = 0; j < 8; j++) {
                int col = wn * 64 + j * 8 + tq * 2;
                float2 v;
                v.x = c[i][j][half * 2 + 0];
                v.y = c[i][j][half * 2 + 1];
                if (bias) {
                    v.x += bias[col];
                    v.y += bias[col + 1];
                }
                if (addsrc) {
                    float2 s = *(const float2*)(addsrc + (size_t)row * HID + col);
                    v.x += s.x; v.y += s.y;
                }
                if (dorelu) {
                    v.x = fmaxf(v.x, 0.f);
                    v.y = fmaxf(v.y, 0.f);
                }
                *(float2*)(C + (size_t)row * HID + col) = v;
            }
        }
    }
}

// ---------------------------------------------------------------------------
// Edge degree count (float, matches segment_sum of ones)
// ---------------------------------------------------------------------------
__global__ void count_kernel(const int* __restrict__ dst, int E, float* __restrict__ cnt)
{
    int e = blockIdx.x * blockDim.x + threadIdx.x;
    if (e < E) atomicAdd(&cnt[dst[e]], 1.0f);
}

__global__ void inv_kernel(float* __restrict__ c, int n)
{
    int i = blockIdx.x * blockDim.x + threadIdx.x;
    if (i < n) c[i] = 1.0f / fmaxf(c[i], 1.0f);
}

// ---------------------------------------------------------------------------
// Combined Wl / bias per (layer, dst type). dst type of relation t:
//   t: 0..7 -> {product,user,query,user,product,query,category,product}
// ---------------------------------------------------------------------------
__global__ void wsum_kernel(const float* __restrict__ W1l, const float* __restrict__ b1,
                            const float* __restrict__ W2l, const float* __restrict__ b2,
                            float* __restrict__ wsum, float* __restrict__ bsum)
{
    const int dstT[8] = {1, 0, 3, 0, 1, 3, 2, 1};
    int idx = blockIdx.x * blockDim.x + threadIdx.x;
    if (idx >= 2 * 4 * HID * HID) return;
    int l  = idx / (4 * HID * HID);
    int r  = idx % (4 * HID * HID);
    int d  = r / (HID * HID);
    int ij = r % (HID * HID);
    const float* W = l ? W2l : W1l;
    float s = 0.f;
#pragma unroll
    for (int t = 0; t < 8; t++)
        if (dstT[t] == d) s += W[t * HID * HID + ij];
    wsum[idx] = s;
    if (ij < HID) {
        const float* B = l ? b2 : b1;
        float sb = 0.f;
#pragma unroll
        for (int t = 0; t < 8; t++)
            if (dstT[t] == d) sb += B[t * HID + ij];
        bsum[(l * 4 + d) * HID + ij] = sb;
    }
}

// ---------------------------------------------------------------------------
// Edge scatter: one warp per edge, vectorized red.global (16B per lane).
//   acc[dst][:] += y[src][:] * (w[e] * inv[dst])
// ---------------------------------------------------------------------------
__global__ void scatter_kernel(const float* __restrict__ y,
                               const int* __restrict__ src_idx,
                               const int* __restrict__ dst_idx,
                               const float* __restrict__ ew,
                               const float* __restrict__ inv,
                               float* __restrict__ acc, int E)
{
    int gw = (blockIdx.x * blockDim.x + threadIdx.x) >> 5;
    int lane = threadIdx.x & 31;
    if (gw >= E) return;
    int s = src_idx[gw];
    int d = dst_idx[gw];
    float sc = ew[gw] * inv[d];
    float4 v = *((const float4*)(y + (size_t)s * HID) + lane);
    float* ar = acc + (size_t)d * HID + lane * 4;
    asm volatile("red.global.add.v4.f32 [%0], {%1,%2,%3,%4};"
                 :: "l"(ar), "f"(v.x * sc), "f"(v.y * sc), "f"(v.z * sc), "f"(v.w * sc)
                 : "memory");
}

// ---------------------------------------------------------------------------
// Host launch
// ---------------------------------------------------------------------------
struct Rel { int srcT, dstT, E, eiIdx, rev, ewIdx, invOff; };

extern "C" void kernel_launch(void* const* d_in, const int* in_sizes, int n_in,
                              void* d_out, int out_size)
{
    (void)in_sizes; (void)n_in; (void)out_size;

    static const Rel rels[8] = {
        {0, 1, 500000, 18, 0, 10, 0},       // user -> product  (buys)
        {1, 0, 500000, 18, 1, 11, 100000},  // product -> user  (rev buys)
        {0, 3, 300000, 19, 0, 12, 300000},  // user -> query    (searches)
        {3, 0, 300000, 19, 1, 13, 350000},  // query -> user    (rev searches)
        {3, 1, 300000, 20, 0, 14, 550000},  // query -> product (matches)
        {1, 3, 300000, 20, 1, 15, 650000},  // product -> query (rev matches)
        {1, 2, 100000, 21, 0, 16, 700000},  // product -> category (in)
        {2, 1, 100000, 21, 1, 17, 702000},  // category -> product (rev in)
    };
    static const int    nodeN[4]   = {NU, NP, NC, NQ};
    static const size_t nodeOff[4] = {0, NU, NU + NP, NU + NP + NC};

    cudaFuncSetAttribute(gemm_mma, cudaFuncAttributeMaxDynamicSharedMemorySize, SMEM_BYTES);

    float *y, *acc, *h, *inv, *wsum, *bsum;
    cudaGetSymbolAddress((void**)&y,    g_y);
    cudaGetSymbolAddress((void**)&acc,  g_acc);
    cudaGetSymbolAddress((void**)&h,    g_h);
    cudaGetSymbolAddress((void**)&inv,  g_inv);
    cudaGetSymbolAddress((void**)&wsum, g_wsum);
    cudaGetSymbolAddress((void**)&bsum, g_bsum);

    const float* x0[4] = { (const float*)d_in[0], (const float*)d_in[1],
                           (const float*)d_in[2], (const float*)d_in[3] };
    const float* W1l = (const float*)d_in[4];
    const float* b1  = (const float*)d_in[5];
    const float* W1r = (const float*)d_in[6];
    const float* W2l = (const float*)d_in[7];
    const float* b2  = (const float*)d_in[8];
    const float* W2r = (const float*)d_in[9];
    float* out = (float*)d_out;

    cudaStream_t st = 0;

    // ---- counts -> inverse (edge structure is layer-invariant) ----
    cudaMemsetAsync(inv, 0, 802000 * sizeof(float), st);
    for (int t = 0; t < 8; t++) {
        const Rel& r = rels[t];
        const int* ei  = (const int*)d_in[r.eiIdx];
        const int* dst = r.rev ? ei : ei + r.E;
        count_kernel<<<(r.E + 255) / 256, 256, 0, st>>>(dst, r.E, inv + r.invOff);
    }
    inv_kernel<<<(802000 + 255) / 256, 256, 0, st>>>(inv, 802000);

    // ---- combined Wl / bias ----
    wsum_kernel<<<(2 * 4 * HID * HID + 255) / 256, 256, 0, st>>>(W1l, b1, W2l, b2, wsum, bsum);

    // ---- two layers ----
    for (int layer = 0; layer < 2; layer++) {
        const float* Wr = layer ? W2r : W1r;
        cudaMemsetAsync(acc, 0, (size_t)NTOT * HID * sizeof(float), st);

        for (int t = 0; t < 8; t++) {
            const Rel& r = rels[t];
            const float* A = layer ? (h + nodeOff[r.srcT] * HID) : x0[r.srcT];
            int nsrc = nodeN[r.srcT];
            gemm_mma<<<(nsrc + 127) / 128, 256, SMEM_BYTES, st>>>(
                A, Wr + t * HID * HID, nullptr, nullptr, y, nsrc, 0);

            const int* ei  = (const int*)d_in[r.eiIdx];
            const int* src = r.rev ? ei + r.E : ei;
            const int* dst = r.rev ? ei       : ei + r.E;
            const float* ew = (const float*)d_in[r.ewIdx];
            scatter_kernel<<<(r.E * 32 + 255) / 256, 256, 0, st>>>(
                y, src, dst, ew, inv + r.invOff, acc + nodeOff[r.dstT] * HID, r.E);
        }

        for (int d = 0; d < 4; d++) {
            const float* A = layer ? (h + nodeOff[d] * HID) : x0[d];
            float* C = layer ? (out + nodeOff[d] * HID) : (h + nodeOff[d] * HID);
            gemm_mma<<<(nodeN[d] + 127) / 128, 256, SMEM_BYTES, st>>>(
                A, wsum + (layer * 4 + d) * HID * HID, acc + nodeOff[d] * HID,
                bsum + (layer * 4 + d) * HID, C, nodeN[d], layer == 0 ? 1 : 0);
        }
    }
}

// round 3
// speedup vs baseline: 2.5140x; 1.2374x over previous
#include <cuda_runtime.h>
#include <cuda_bf16.h>
#include <stdint.h>

// ---------------------------------------------------------------------------
// HeteroGraphSAGE, 2 layers, 4 node types, 8 relations.
// Node layout (concatenated): user[200000] | product[100000] | category[2000] | query[50000]
//
// Key algebra: agg[d] = inv[d] * sum_e w_e * (Wr x[src]) = Wr * (inv[d] * sum_e w_e * x[src])
// -> aggregate RAW 128-d features with a CSR gather (no atomics), then fold all
//    transforms for a dst type into ONE K-concatenated tensor-core GEMM.
// ---------------------------------------------------------------------------

#define NU 200000
#define NP 100000
#define NC 2000
#define NQ 50000
#define NTOT 352000
#define HID 128

#define NROWS 802000        // total (relation, dst-node) rows
#define ETOT  2400000       // total directed edges

#define LDS 72              // bf16 elems per smem row (64 data + 8 pad -> 144B stride)
#define LDSB 144
#define SMEM_BYTES (4 * 128 * LDS * 2)   // Ah, Al, Wh, Wl

// scratch (device globals; allocation-free)
__device__ float g_aggr[(size_t)NROWS * HID];    // per-(relation,dst) aggregated raw features
__device__ float g_h[(size_t)NTOT * HID];        // hidden after layer 1
__device__ int   g_cnt[NROWS];                   // per-row degree
__device__ int   g_rowptr[NROWS + 1];            // CSR row pointers (global over relations)
__device__ int   g_cursor[NROWS];                // fill cursors
__device__ int   g_srcg[ETOT];                   // CSR: type-local src index
__device__ float g_wg[ETOT];                     // CSR: edge weight
__device__ int   g_bsums[512];                   // scan partials
__device__ float g_wsum[2 * 4 * HID * HID];      // combined Wl per (layer, dst type)
__device__ float g_bsum[2 * 4 * HID];            // combined bias per (layer, dst type)

// ---------------------------------------------------------------------------
// PTX helpers
// ---------------------------------------------------------------------------
#define LDSM4(R, addr)                                                          \
    asm volatile("ldmatrix.sync.aligned.m8n8.x4.shared.b16 {%0,%1,%2,%3}, [%4];" \
                 : "=r"((R)[0]), "=r"((R)[1]), "=r"((R)[2]), "=r"((R)[3])        \
                 : "r"(addr))

#define MMA16816(C, A, B0, B1)                                                  \
    asm volatile("mma.sync.aligned.m16n8k16.row.col.f32.bf16.bf16.f32 "         \
                 "{%0,%1,%2,%3},{%4,%5,%6,%7},{%8,%9},{%0,%1,%2,%3};"           \
                 : "+f"((C)[0]), "+f"((C)[1]), "+f"((C)[2]), "+f"((C)[3])        \
                 : "r"((A)[0]), "r"((A)[1]), "r"((A)[2]), "r"((A)[3]),           \
                   "r"(B0), "r"(B1))

__device__ __forceinline__ uint32_t pack_bf16(__nv_bfloat16 a, __nv_bfloat16 b)
{
    __nv_bfloat162 p = __halves2bfloat162(a, b);
    return *reinterpret_cast<uint32_t*>(&p);
}

__device__ __forceinline__ void split_pair(float x, float y, uint32_t& hi, uint32_t& lo)
{
    __nv_bfloat16 hx = __float2bfloat16(x);
    __nv_bfloat16 hy = __float2bfloat16(y);
    __nv_bfloat16 lx = __float2bfloat16(x - __bfloat162float(hx));
    __nv_bfloat16 ly = __float2bfloat16(y - __bfloat162float(hy));
    hi = pack_bf16(hx, hy);
    lo = pack_bf16(lx, ly);
}

// ---------------------------------------------------------------------------
// Multi-chunk tensor-core GEMM (bf16x3 split, fp32-accurate to ~2^-16):
//   C[i][:] = bias[:] + sum_ch A_ch[i][:] @ W_ch^T   (each chunk K=128, N=128)
// Block tile 128x128, warp tile 32x64 (8 warps), K sub-chunked by 64.
// ---------------------------------------------------------------------------
struct ChunkPtrs {
    const float* A0; const float* A1; const float* A2; const float* A3;
    const float* W0; const float* W1; const float* W2; const float* W3;
};

__global__ void __launch_bounds__(256, 2)
gemm_mma(ChunkPtrs p, int nch, const float* __restrict__ bias,
         float* __restrict__ C, int n, int dorelu)
{
    extern __shared__ __nv_bfloat16 smem[];
    uint32_t sAh_u = (uint32_t)__cvta_generic_to_shared(smem);
    const uint32_t LO_OFF = 128 * LDS * 2;       // bytes from hi array to lo array
    uint32_t sWh_u = sAh_u + 2 * LO_OFF;

    const int tid  = threadIdx.x;
    const int lane = tid & 31;
    const int warp = tid >> 5;
    const int wm = warp >> 1;       // 0..3  (rows)
    const int wn = warp & 1;        // 0..1  (cols)
    const int bm = blockIdx.x * 128;

    float c[2][8][4];
#pragma unroll
    for (int i = 0; i < 2; i++)
#pragma unroll
        for (int j = 0; j < 8; j++)
#pragma unroll
            for (int q = 0; q < 4; q++) c[i][j][q] = 0.f;

#pragma unroll
    for (int ch = 0; ch < 4; ch++) {
        if (ch >= nch) break;
        const float* A = (ch == 0) ? p.A0 : (ch == 1) ? p.A1 : (ch == 2) ? p.A2 : p.A3;
        const float* W = (ch == 0) ? p.W0 : (ch == 1) ? p.W1 : (ch == 2) ? p.W2 : p.W3;

        for (int kb = 0; kb < 128; kb += 64) {
            // ---- load + convert A chunk (128 x 64) and W chunk (128 x 64) ----
#pragma unroll
            for (int it = 0; it < 8; it++) {
                int idx = tid + it * 256;          // float4 id 0..2047
                int r   = idx >> 4;                // row 0..127
                int kc  = (idx & 15) << 2;         // k within chunk, mult of 4

                float4 va = make_float4(0.f, 0.f, 0.f, 0.f);
                int row = bm + r;
                if (row < n)
                    va = *(const float4*)(A + (size_t)row * HID + kb + kc);
                uint32_t h01, l01, h23, l23;
                split_pair(va.x, va.y, h01, l01);
                split_pair(va.z, va.w, h23, l23);
                size_t so = (size_t)r * LDS + kc;
                *(uint2*)(smem + so)                 = make_uint2(h01, h23);
                *(uint2*)(smem + 128 * LDS + so)     = make_uint2(l01, l23);

                float4 vw = *(const float4*)(W + (size_t)r * HID + kb + kc);
                split_pair(vw.x, vw.y, h01, l01);
                split_pair(vw.z, vw.w, h23, l23);
                *(uint2*)(smem + 2 * 128 * LDS + so) = make_uint2(h01, h23);
                *(uint2*)(smem + 3 * 128 * LDS + so) = make_uint2(l01, l23);
            }
            __syncthreads();

            // ---- 4 k-steps of 16 within this 64-chunk ----
#pragma unroll
            for (int ks = 0; ks < 4; ks++) {
                uint32_t ah[2][4], al[2][4], bh[4][4], bl[4][4];

#pragma unroll
                for (int i = 0; i < 2; i++) {
                    int r   = wm * 32 + i * 16 + (lane & 15);
                    int kby = ks * 32 + ((lane >> 4) << 4);
                    uint32_t ad = sAh_u + r * LDSB + kby;
                    LDSM4(ah[i], ad);
                    LDSM4(al[i], ad + LO_OFF);
                }
#pragma unroll
                for (int pq = 0; pq < 4; pq++) {
                    int nr  = wn * 64 + (2 * pq + (lane >> 4)) * 8 + (lane & 7);
                    int kby = ks * 32 + ((lane >> 3) & 1) * 16;
                    uint32_t ad = sWh_u + nr * LDSB + kby;
                    LDSM4(bh[pq], ad);
                    LDSM4(bl[pq], ad + LO_OFF);
                }

#pragma unroll
                for (int i = 0; i < 2; i++)
#pragma unroll
                    for (int j = 0; j < 8; j++) {
                        const uint32_t* b = bh[j >> 1] + (j & 1) * 2;
                        MMA16816(c[i][j], ah[i], b[0], b[1]);
                    }
#pragma unroll
                for (int i = 0; i < 2; i++)
#pragma unroll
                    for (int j = 0; j < 8; j++) {
                        const uint32_t* b = bl[j >> 1] + (j & 1) * 2;
                        MMA16816(c[i][j], ah[i], b[0], b[1]);
                    }
#pragma unroll
                for (int i = 0; i < 2; i++)
#pragma unroll
                    for (int j = 0; j < 8; j++) {
                        const uint32_t* b = bh[j >> 1] + (j & 1) * 2;
                        MMA16816(c[i][j], al[i], b[0], b[1]);
                    }
            }
            __syncthreads();
        }
    }

    // ---- epilogue ----
    const int g  = lane >> 2;
    const int tq = lane & 3;
#pragma unroll
    for (int i = 0; i < 2; i++) {
#pragma unroll
        for (int half = 0; half < 2; half++) {
            int row = bm + wm * 32 + i * 16 + half * 8 + g;
            if (row >= n) continue;
#pragma unroll
            for (int j = 0; j < 8; j++) {
                int col = wn * 64 + j * 8 + tq * 2;
                float2 v;
                v.x = c[i][j][half * 2 + 0] + bias[col];
                v.y = c[i][j][half * 2 + 1] + bias[col + 1];
                if (dorelu) {
                    v.x = fmaxf(v.x, 0.f);
                    v.y = fmaxf(v.y, 0.f);
                }
                *(float2*)(C + (size_t)row * HID + col) = v;
            }
        }
    }
}

// ---------------------------------------------------------------------------
// CSR build: count -> scan -> fill
// ---------------------------------------------------------------------------
__global__ void count_kernel(const int* __restrict__ dst, int E, int* __restrict__ cnt)
{
    int e = blockIdx.x * blockDim.x + threadIdx.x;
    if (e < E) atomicAdd(&cnt[dst[e]], 1);
}

// scan1: per-block (4096 elems) exclusive scan; block sums out
__global__ void scan1_kernel(const int* __restrict__ cnt, int* __restrict__ rowptr,
                             int* __restrict__ bsums, int n)
{
    __shared__ int wsums[8];
    int base = blockIdx.x * 4096 + threadIdx.x * 16;
    int v[16];
    int s = 0;
#pragma unroll
    for (int i = 0; i < 16; i++) {
        v[i] = (base + i < n) ? cnt[base + i] : 0;
        s += v[i];
    }
    int lane = threadIdx.x & 31, w = threadIdx.x >> 5;
    int ps = s;
#pragma unroll
    for (int o = 1; o < 32; o <<= 1) {
        int t = __shfl_up_sync(0xffffffffu, ps, o);
        if (lane >= o) ps += t;
    }
    if (lane == 31) wsums[w] = ps;
    __syncthreads();
    if (w == 0) {
        int t = (lane < 8) ? wsums[lane] : 0;
#pragma unroll
        for (int o = 1; o < 8; o <<= 1) {
            int u = __shfl_up_sync(0xffffffffu, t, o);
            if (lane >= o) t += u;
        }
        if (lane < 8) wsums[lane] = t;
    }
    __syncthreads();
    int excl = ps - s + (w ? wsums[w - 1] : 0);
    int run = excl;
#pragma unroll
    for (int i = 0; i < 16; i++) {
        if (base + i < n) rowptr[base + i] = run;
        run += v[i];
    }
    if (threadIdx.x == 0) bsums[blockIdx.x] = wsums[7];
}

// scan2: exclusive scan of block sums (single thread; nb ~ 196)
__global__ void scan2_kernel(int* __restrict__ bsums, int nb)
{
    if (threadIdx.x == 0 && blockIdx.x == 0) {
        int run = 0;
        for (int i = 0; i < nb; i++) {
            int t = bsums[i];
            bsums[i] = run;
            run += t;
        }
    }
}

// scan3: add block offsets; set rowptr[NROWS]
__global__ void scan3_kernel(int* __restrict__ rowptr, const int* __restrict__ bsums, int n)
{
    int base = blockIdx.x * 4096 + threadIdx.x * 16;
    int off = bsums[blockIdx.x];
#pragma unroll
    for (int i = 0; i < 16; i++)
        if (base + i < n) rowptr[base + i] += off;
    if (blockIdx.x == 0 && threadIdx.x == 0) rowptr[n] = ETOT;
}

__global__ void fill_kernel(const int* __restrict__ src, const int* __restrict__ dst,
                            const float* __restrict__ ew, int E, int rowOff,
                            int* __restrict__ cursor,
                            int* __restrict__ srcg, float* __restrict__ wg)
{
    int e = blockIdx.x * blockDim.x + threadIdx.x;
    if (e >= E) return;
    int slot = atomicAdd(&cursor[rowOff + dst[e]], 1);
    srcg[slot] = src[e];
    wg[slot]   = ew[e];
}

// ---------------------------------------------------------------------------
// Combined Wl / bias per (layer, dst type). dst type of relation t:
//   t: 0..7 -> {product,user,query,user,product,query,category,product}
// ---------------------------------------------------------------------------
__global__ void wsum_kernel(const float* __restrict__ W1l, const float* __restrict__ b1,
                            const float* __restrict__ W2l, const float* __restrict__ b2,
                            float* __restrict__ wsum, float* __restrict__ bsum)
{
    const int dstT[8] = {1, 0, 3, 0, 1, 3, 2, 1};
    int idx = blockIdx.x * blockDim.x + threadIdx.x;
    if (idx >= 2 * 4 * HID * HID) return;
    int l  = idx / (4 * HID * HID);
    int r  = idx % (4 * HID * HID);
    int d  = r / (HID * HID);
    int ij = r % (HID * HID);
    const float* W = l ? W2l : W1l;
    float s = 0.f;
#pragma unroll
    for (int t = 0; t < 8; t++)
        if (dstT[t] == d) s += W[t * HID * HID + ij];
    wsum[idx] = s;
    if (ij < HID) {
        const float* B = l ? b2 : b1;
        float sb = 0.f;
#pragma unroll
        for (int t = 0; t < 8; t++)
            if (dstT[t] == d) sb += B[t * HID + ij];
        bsum[(l * 4 + d) * HID + ij] = sb;
    }
}

// ---------------------------------------------------------------------------
// CSR gather: one warp per (relation,dst) row — NO atomics.
//   aggr[row][:] = (1/max(deg,1)) * sum_e w_e * x[src_e][:]
// ---------------------------------------------------------------------------
__global__ void gather_kernel(const float* __restrict__ x,
                              const int* __restrict__ rowptr,
                              const int* __restrict__ srcg,
                              const float* __restrict__ wg,
                              float* __restrict__ aggr, int nrows, int rowOff)
{
    int row = (blockIdx.x * blockDim.x + threadIdx.x) >> 5;
    int lane = threadIdx.x & 31;
    if (row >= nrows) return;
    int g = rowOff + row;
    int e0 = rowptr[g], e1 = rowptr[g + 1];

    float4 acc = make_float4(0.f, 0.f, 0.f, 0.f);
    int e = e0;
    for (; e + 1 < e1; e += 2) {
        int   s0 = srcg[e],   s1 = srcg[e + 1];
        float w0 = wg[e],     w1 = wg[e + 1];
        float4 v0 = *((const float4*)(x + (size_t)s0 * HID) + lane);
        float4 v1 = *((const float4*)(x + (size_t)s1 * HID) + lane);
        acc.x += w0 * v0.x + w1 * v1.x;
        acc.y += w0 * v0.y + w1 * v1.y;
        acc.z += w0 * v0.z + w1 * v1.z;
        acc.w += w0 * v0.w + w1 * v1.w;
    }
    if (e < e1) {
        int s0 = srcg[e];
        float w0 = wg[e];
        float4 v0 = *((const float4*)(x + (size_t)s0 * HID) + lane);
        acc.x += w0 * v0.x;
        acc.y += w0 * v0.y;
        acc.z += w0 * v0.z;
        acc.w += w0 * v0.w;
    }
    float invd = 1.f / fmaxf((float)(e1 - e0), 1.f);
    acc.x *= invd; acc.y *= invd; acc.z *= invd; acc.w *= invd;
    *((float4*)(aggr + (size_t)g * HID) + lane) = acc;
}

// ---------------------------------------------------------------------------
// Host launch
// ---------------------------------------------------------------------------
struct Rel { int srcT, dstT, E, eiIdx, rev, ewIdx, rowOff; };

extern "C" void kernel_launch(void* const* d_in, const int* in_sizes, int n_in,
                              void* d_out, int out_size)
{
    (void)in_sizes; (void)n_in; (void)out_size;

    static const Rel rels[8] = {
        {0, 1, 500000, 18, 0, 10, 0},       // user -> product  (buys)
        {1, 0, 500000, 18, 1, 11, 100000},  // product -> user  (rev buys)
        {0, 3, 300000, 19, 0, 12, 300000},  // user -> query    (searches)
        {3, 0, 300000, 19, 1, 13, 350000},  // query -> user    (rev searches)
        {3, 1, 300000, 20, 0, 14, 550000},  // query -> product (matches)
        {1, 3, 300000, 20, 1, 15, 650000},  // product -> query (rev matches)
        {1, 2, 100000, 21, 0, 16, 700000},  // product -> category (in)
        {2, 1, 100000, 21, 1, 17, 702000},  // category -> product (rev in)
    };
    // relations targeting each dst type (for the K-concat GEMM)
    static const int relForDst[4][3] = { {1, 3, -1}, {0, 4, 7}, {6, -1, -1}, {2, 5, -1} };
    static const int nRelForDst[4]   = { 2, 3, 1, 2 };
    static const int    nodeN[4]   = {NU, NP, NC, NQ};
    static const size_t nodeOff[4] = {0, NU, NU + NP, NU + NP + NC};

    cudaFuncSetAttribute(gemm_mma, cudaFuncAttributeMaxDynamicSharedMemorySize, SMEM_BYTES);

    float *aggr, *h, *wsum, *bsum, *wg;
    int *cnt, *rowptr, *cursor, *srcg, *bsums;
    cudaGetSymbolAddress((void**)&aggr,   g_aggr);
    cudaGetSymbolAddress((void**)&h,      g_h);
    cudaGetSymbolAddress((void**)&cnt,    g_cnt);
    cudaGetSymbolAddress((void**)&rowptr, g_rowptr);
    cudaGetSymbolAddress((void**)&cursor, g_cursor);
    cudaGetSymbolAddress((void**)&srcg,   g_srcg);
    cudaGetSymbolAddress((void**)&wg,     g_wg);
    cudaGetSymbolAddress((void**)&bsums,  g_bsums);
    cudaGetSymbolAddress((void**)&wsum,   g_wsum);
    cudaGetSymbolAddress((void**)&bsum,   g_bsum);

    const float* x0[4] = { (const float*)d_in[0], (const float*)d_in[1],
                           (const float*)d_in[2], (const float*)d_in[3] };
    const float* W1l = (const float*)d_in[4];
    const float* b1  = (const float*)d_in[5];
    const float* W1r = (const float*)d_in[6];
    const float* W2l = (const float*)d_in[7];
    const float* b2  = (const float*)d_in[8];
    const float* W2r = (const float*)d_in[9];
    float* out = (float*)d_out;

    cudaStream_t st = 0;
    const int NSCAN = (NROWS + 4095) / 4096;

    // ---- CSR build (edge structure is layer-invariant) ----
    cudaMemsetAsync(cnt, 0, NROWS * sizeof(int), st);
    for (int t = 0; t < 8; t++) {
        const Rel& r = rels[t];
        const int* ei  = (const int*)d_in[r.eiIdx];
        const int* dst = r.rev ? ei : ei + r.E;
        count_kernel<<<(r.E + 255) / 256, 256, 0, st>>>(dst, r.E, cnt + r.rowOff);
    }
    scan1_kernel<<<NSCAN, 256, 0, st>>>(cnt, rowptr, bsums, NROWS);
    scan2_kernel<<<1, 32, 0, st>>>(bsums, NSCAN);
    scan3_kernel<<<NSCAN, 256, 0, st>>>(rowptr, bsums, NROWS);
    cudaMemcpyAsync(cursor, rowptr, NROWS * sizeof(int), cudaMemcpyDeviceToDevice, st);
    for (int t = 0; t < 8; t++) {
        const Rel& r = rels[t];
        const int* ei  = (const int*)d_in[r.eiIdx];
        const int* src = r.rev ? ei + r.E : ei;
        const int* dst = r.rev ? ei       : ei + r.E;
        const float* ew = (const float*)d_in[r.ewIdx];
        fill_kernel<<<(r.E + 255) / 256, 256, 0, st>>>(src, dst, ew, r.E, r.rowOff,
                                                       cursor, srcg, wg);
    }

    // ---- combined Wl / bias ----
    wsum_kernel<<<(2 * 4 * HID * HID + 255) / 256, 256, 0, st>>>(W1l, b1, W2l, b2, wsum, bsum);

    // ---- two layers ----
    for (int layer = 0; layer < 2; layer++) {
        const float* Wr = layer ? W2r : W1r;

        // gather raw features per relation (no atomics)
        for (int t = 0; t < 8; t++) {
            const Rel& r = rels[t];
            const float* x = layer ? (h + nodeOff[r.srcT] * HID) : x0[r.srcT];
            int nrows = nodeN[r.dstT];
            gather_kernel<<<(nrows * 32 + 255) / 256, 256, 0, st>>>(
                x, rowptr, srcg, wg, aggr, nrows, r.rowOff);
        }

        // one K-concat GEMM per dst type: [x_d | aggr_t...] @ [Wsum_d ; Wr_t...]^T
        for (int d = 0; d < 4; d++) {
            ChunkPtrs p;
            p.A0 = layer ? (h + nodeOff[d] * HID) : x0[d];
            p.W0 = wsum + (layer * 4 + d) * HID * HID;
            const float* As[3] = {nullptr, nullptr, nullptr};
            const float* Ws[3] = {nullptr, nullptr, nullptr};
            for (int q = 0; q < nRelForDst[d]; q++) {
                int t = relForDst[d][q];
                As[q] = aggr + (size_t)rels[t].rowOff * HID;
                Ws[q] = Wr + t * HID * HID;
            }
            p.A1 = As[0]; p.A2 = As[1]; p.A3 = As[2];
            p.W1 = Ws[0]; p.W2 = Ws[1]; p.W3 = Ws[2];
            int nch = 1 + nRelForDst[d];
            float* C = layer ? (out + nodeOff[d] * HID) : (h + nodeOff[d] * HID);
            gemm_mma<<<(nodeN[d] + 127) / 128, 256, SMEM_BYTES, st>>>(
                p, nch, bsum + (layer * 4 + d) * HID, C, nodeN[d], layer == 0 ? 1 : 0);
        }
    }
}